// round 6
// baseline (speedup 1.0000x reference)
#include <cuda_runtime.h>
#include <cuda_bf16.h>
#include <stdint.h>

#define DI __device__ __forceinline__

static constexpr int BATCH  = 4096;
static constexpr int DM     = 2048;
static constexpr int NEXP   = 8;
static constexpr int KS     = 3 * DM;       // 6144 logical split-K (k-loop extent)
static constexpr int WK     = 2 * DM;       // 4096 dedup'd storage width [hi|lo]
static constexpr int BM     = 256;
static constexpr int BN     = 128;
static constexpr int BK     = 64;           // bf16 per k-tile (128B row)
static constexpr int KT     = KS / BK;      // 96 k-tiles (32 per product term)
static constexpr int STAGES = 4;
static constexpr int NTHR   = 256;

static constexpr int A_BYTES     = BM * 128;              // 32768
static constexpr int B_BYTES     = BN * 128;              // 16384
static constexpr int STAGE_BYTES = A_BYTES + B_BYTES;     // 49152
static constexpr int SMEM_STAGES = STAGES * STAGE_BYTES;  // 196608
static constexpr int SMEM_REQ    = SMEM_STAGES + 1024;

// ---------------- device scratch (dedup: hi stored once) ----------------
__device__ __nv_bfloat16 g_W [(unsigned long long)3 * DM * WK];   // [wh|wl] per layer row
__device__ __nv_bfloat16 g_Xa[(unsigned long long)BATCH * WK];    // [xh|xl] ping
__device__ __nv_bfloat16 g_Xb[(unsigned long long)BATCH * WK];    // [xh|xl] pong

// ---------------- helpers ----------------
DI uint32_t smem_u32(const void* p) {
    uint32_t a;
    asm("{ .reg .u64 t; cvta.to.shared.u64 t, %1; cvt.u32.u64 %0, t; }" : "=r"(a) : "l"(p));
    return a;
}
DI uint32_t swz(uint32_t off) { return off ^ ((off >> 3) & 0x70); }  // SW128

DI void cp16(uint32_t s, const void* g) {
    asm volatile("cp.async.cg.shared.global [%0], [%1], 16;\n" :: "r"(s), "l"(g));
}
DI void cp_commit() { asm volatile("cp.async.commit_group;\n" ::); }
template <int N> DI void cp_wait() { asm volatile("cp.async.wait_group %0;\n" :: "n"(N)); }

DI void ldsm4(uint32_t& r0, uint32_t& r1, uint32_t& r2, uint32_t& r3, uint32_t addr) {
    asm volatile("ldmatrix.sync.aligned.m8n8.x4.shared.b16 {%0,%1,%2,%3}, [%4];"
                 : "=r"(r0), "=r"(r1), "=r"(r2), "=r"(r3) : "r"(addr));
}
DI void mma16816(float* d, uint32_t a0, uint32_t a1, uint32_t a2, uint32_t a3,
                 uint32_t b0, uint32_t b1) {
    asm volatile(
        "mma.sync.aligned.m16n8k16.row.col.f32.bf16.bf16.f32 "
        "{%0,%1,%2,%3}, {%4,%5,%6,%7}, {%8,%9}, {%0,%1,%2,%3};"
        : "+f"(d[0]), "+f"(d[1]), "+f"(d[2]), "+f"(d[3])
        : "r"(a0), "r"(a1), "r"(a2), "r"(a3), "r"(b0), "r"(b1));
}

DI uint32_t pack_bf2(__nv_bfloat16 a, __nv_bfloat16 b) {
    return (uint32_t)__bfloat16_as_ushort(a) | ((uint32_t)__bfloat16_as_ushort(b) << 16);
}
DI void split1(float v, __nv_bfloat16& h, __nv_bfloat16& l) {
    h = __float2bfloat16(v);
    l = __float2bfloat16(v - __bfloat162float(h));
}

// ---------------- blend: Wd[l] = [wh | wl] of sum_e c_e W[l,e] ----------------
__global__ void blend_kernel(const float* __restrict__ coef, const float* __restrict__ W) {
    long long idx = (long long)blockIdx.x * blockDim.x + threadIdx.x;
    const long long total = 3LL * DM * (DM / 4);
    if (idx >= total) return;
    int       i4 = (int)(idx % (DM / 4));
    long long t  = idx / (DM / 4);
    int       o  = (int)(t % DM);
    int       l  = (int)(t / DM);

    float c[NEXP];
#pragma unroll
    for (int e = 0; e < NEXP; ++e) c[e] = __ldg(coef + e);

    const float* base = W + ((size_t)l * NEXP) * DM * DM + (size_t)o * DM + (size_t)i4 * 4;
    float4 acc = make_float4(0.f, 0.f, 0.f, 0.f);
#pragma unroll
    for (int e = 0; e < NEXP; ++e) {
        float4 v = __ldg((const float4*)(base + (size_t)e * DM * DM));
        acc.x += c[e] * v.x; acc.y += c[e] * v.y;
        acc.z += c[e] * v.z; acc.w += c[e] * v.w;
    }
    __nv_bfloat16 h[4], lo[4];
    split1(acc.x, h[0], lo[0]); split1(acc.y, h[1], lo[1]);
    split1(acc.z, h[2], lo[2]); split1(acc.w, h[3], lo[3]);

    __nv_bfloat16* row = g_W + ((size_t)l * DM + o) * WK;
    int n = i4 * 4;
    uint2 hv = { pack_bf2(h[0], h[1]),  pack_bf2(h[2], h[3]) };
    uint2 lv = { pack_bf2(lo[0], lo[1]), pack_bf2(lo[2], lo[3]) };
    *(uint2*)&row[n]      = hv;   // wh
    *(uint2*)&row[DM + n] = lv;   // wl
}

// ---------------- split input x -> Xa = [xh | xl] ----------------
__global__ void splitx_kernel(const float* __restrict__ x) {
    long long idx = (long long)blockIdx.x * blockDim.x + threadIdx.x;
    const long long total = (long long)BATCH * (DM / 4);
    if (idx >= total) return;
    int i4 = (int)(idx % (DM / 4));
    int r  = (int)(idx / (DM / 4));
    float4 v = __ldg((const float4*)(x + (size_t)r * DM) + i4);
    __nv_bfloat16 h[4], lo[4];
    split1(v.x, h[0], lo[0]); split1(v.y, h[1], lo[1]);
    split1(v.z, h[2], lo[2]); split1(v.w, h[3], lo[3]);
    __nv_bfloat16* row = g_Xa + (size_t)r * WK;
    int n = i4 * 4;
    *(uint2*)&row[n]      = make_uint2(pack_bf2(h[0], h[1]),  pack_bf2(h[2], h[3]));
    *(uint2*)&row[DM + n] = make_uint2(pack_bf2(lo[0], lo[1]), pack_bf2(lo[2], lo[3]));
}

// ---------------- GEMM: 256x128 tile, logical K=6144 over dedup'd [hi|lo] ----------------
// Product schedule: t in [0,32): xh*wh; [32,64): xh*wl; [64,96): xl*wh.
// Tile-index remap into 4096-wide storage:  tA = t<32 ? t : t-32 ;  tB = t<64 ? t : t-64.
// 8 warps, warp tile 64x64: warp grid 4(m) x 2(n).
__global__ void __launch_bounds__(NTHR, 1)
gemm_kernel(int src_sel, int layer, const float* __restrict__ bias_all,
            float* __restrict__ out_f) {
    const __nv_bfloat16* A  = src_sel ? g_Xb : g_Xa;
    __nv_bfloat16*       Xn = src_sel ? g_Xa : g_Xb;
    const __nv_bfloat16* Bw = g_W + (size_t)layer * DM * WK;
    const float*         bias = bias_all + layer * DM;
    const bool final_layer = (out_f != nullptr);

    extern __shared__ char smraw[];
    uint32_t sb = (smem_u32(smraw) + 1023u) & ~1023u;

    const int tid  = threadIdx.x;
    const int wid  = tid >> 5;
    const int lane = tid & 31;
    const int wm   = wid & 3;         // m warp (64 rows each)
    const int wn   = wid >> 2;        // n warp (64 cols each)
    const int m_base = blockIdx.y * BM;
    const int n_base = blockIdx.x * BN;

    // ---- cp.async geometry: 16B chunk (tid&7), base row tid>>3, +32 rows per j ----
    const int r0 = tid >> 3;
    const int cbyte = (tid & 7) * 16;
    const char* gA = (const char*)(A  + (size_t)(m_base + r0) * WK) + cbyte;
    const char* gB = (const char*)(Bw + (size_t)(n_base + r0) * WK) + cbyte;
    uint32_t sA[8], sBv[4];
#pragma unroll
    for (int j = 0; j < 8; ++j) sA[j]  = swz((uint32_t)(r0 + 32 * j) * 128 + cbyte);
#pragma unroll
    for (int j = 0; j < 4; ++j) sBv[j] = swz((uint32_t)(r0 + 32 * j) * 128 + cbyte);
    const size_t rowstep = (size_t)32 * WK * 2;   // 32 rows in bytes

#define LOAD_TILE(T)                                                             \
    do {                                                                         \
        int _t  = (T);                                                           \
        int _ta = (_t < 32) ? _t : _t - 32;   /* A: [xh|xl] remap */             \
        int _tb = (_t < 64) ? _t : _t - 64;   /* B: [wh|wl] remap */             \
        int _s = _t & 3;                                                         \
        uint32_t _sa = sb + _s * STAGE_BYTES;                                    \
        uint32_t _sb = _sa + A_BYTES;                                            \
        const char* _ga = gA + (size_t)_ta * (BK * 2);                           \
        const char* _gb = gB + (size_t)_tb * (BK * 2);                           \
        _Pragma("unroll")                                                        \
        for (int _j = 0; _j < 8; ++_j) cp16(_sa + sA[_j], _ga + _j * rowstep);   \
        _Pragma("unroll")                                                        \
        for (int _j = 0; _j < 4; ++_j) cp16(_sb + sBv[_j], _gb + _j * rowstep);  \
        cp_commit();                                                             \
    } while (0)

    // ---- ldmatrix geometry ----
    const int t4  = lane >> 3;
    const int r8  = lane & 7;
    const uint32_t xorw = (uint32_t)r8 << 4;   // swizzle XOR (row&7)<<4
    uint32_t aoff[4], boff[4];
#pragma unroll
    for (int mi = 0; mi < 4; ++mi) {
        int row = wm * 64 + mi * 16 + (t4 & 1) * 8 + r8;
        aoff[mi] = (uint32_t)row * 128 + (uint32_t)(t4 >> 1) * 16;
    }
#pragma unroll
    for (int np = 0; np < 4; ++np) {
        int row = wn * 64 + np * 16 + (t4 >> 1) * 8 + r8;
        boff[np] = (uint32_t)row * 128 + (uint32_t)(t4 & 1) * 16;
    }

    float acc[4][8][4];
#pragma unroll
    for (int i = 0; i < 4; ++i)
#pragma unroll
        for (int j = 0; j < 8; ++j)
#pragma unroll
            for (int q = 0; q < 4; ++q) acc[i][j][q] = 0.f;

    // ---- pipeline ----
    LOAD_TILE(0); LOAD_TILE(1); LOAD_TILE(2);

    for (int t = 0; t < KT; ++t) {
        int rem = KT - 1 - t;
        if (rem >= 2)      cp_wait<2>();
        else if (rem == 1) cp_wait<1>();
        else               cp_wait<0>();
        __syncthreads();
        if (t + 3 < KT) LOAD_TILE(t + 3);

        uint32_t sa = sb + (t & 3) * STAGE_BYTES;
        uint32_t sB = sa + A_BYTES;
#pragma unroll
        for (int k16 = 0; k16 < 4; ++k16) {
            uint32_t a[4][4];
#pragma unroll
            for (int mi = 0; mi < 4; ++mi)
                ldsm4(a[mi][0], a[mi][1], a[mi][2], a[mi][3],
                      sa + ((aoff[mi] + k16 * 32) ^ xorw));
            uint32_t b[4][4];
#pragma unroll
            for (int np = 0; np < 4; ++np)
                ldsm4(b[np][0], b[np][1], b[np][2], b[np][3],
                      sB + ((boff[np] + k16 * 32) ^ xorw));
#pragma unroll
            for (int mi = 0; mi < 4; ++mi)
#pragma unroll
                for (int np = 0; np < 4; ++np) {
                    mma16816(acc[mi][2 * np],     a[mi][0], a[mi][1], a[mi][2], a[mi][3],
                             b[np][0], b[np][1]);
                    mma16816(acc[mi][2 * np + 1], a[mi][0], a[mi][1], a[mi][2], a[mi][3],
                             b[np][2], b[np][3]);
                }
        }
    }

    // ---- epilogue ----
    const int gid = lane >> 2;
    const int tig = lane & 3;

    float bw0[8], bw1[8];
#pragma unroll
    for (int nj = 0; nj < 8; ++nj) {
        int col = n_base + wn * 64 + nj * 8 + 2 * tig;
        bw0[nj] = __ldg(bias + col);
        bw1[nj] = __ldg(bias + col + 1);
    }

    if (!final_layer) {
#pragma unroll
        for (int mi = 0; mi < 4; ++mi) {
            int row0 = m_base + wm * 64 + mi * 16 + gid;
            __nv_bfloat16* xr0 = Xn + (size_t)row0 * WK;
            __nv_bfloat16* xr1 = Xn + (size_t)(row0 + 8) * WK;
#pragma unroll
            for (int nj = 0; nj < 8; ++nj) {
                int n = wn * 64 + nj * 8 + 2 * tig + n_base;
                float v0 = acc[mi][nj][0] + bw0[nj];
                float v1 = acc[mi][nj][1] + bw1[nj];
                float v2 = acc[mi][nj][2] + bw0[nj];
                float v3 = acc[mi][nj][3] + bw1[nj];
                v0 = (v0 > 0.f) ? v0 : expm1f(v0);
                v1 = (v1 > 0.f) ? v1 : expm1f(v1);
                v2 = (v2 > 0.f) ? v2 : expm1f(v2);
                v3 = (v3 > 0.f) ? v3 : expm1f(v3);
                __nv_bfloat16 h0, l0, h1, l1, h2, l2, h3, l3;
                split1(v0, h0, l0); split1(v1, h1, l1);
                split1(v2, h2, l2); split1(v3, h3, l3);
                *(uint32_t*)&xr0[n]      = pack_bf2(h0, h1);
                *(uint32_t*)&xr0[DM + n] = pack_bf2(l0, l1);
                *(uint32_t*)&xr1[n]      = pack_bf2(h2, h3);
                *(uint32_t*)&xr1[DM + n] = pack_bf2(l2, l3);
            }
        }
    } else {
#pragma unroll
        for (int mi = 0; mi < 4; ++mi) {
            int row0 = m_base + wm * 64 + mi * 16 + gid;
            float* o0 = out_f + (size_t)row0 * DM;
            float* o1 = out_f + (size_t)(row0 + 8) * DM;
#pragma unroll
            for (int nj = 0; nj < 8; ++nj) {
                int n = n_base + wn * 64 + nj * 8 + 2 * tig;
                float2 u0 = { acc[mi][nj][0] + bw0[nj], acc[mi][nj][1] + bw1[nj] };
                float2 u1 = { acc[mi][nj][2] + bw0[nj], acc[mi][nj][3] + bw1[nj] };
                *(float2*)&o0[n] = u0;
                *(float2*)&o1[n] = u1;
            }
        }
    }
#undef LOAD_TILE
}

// ---------------- host launch ----------------
extern "C" void kernel_launch(void* const* d_in, const int* in_sizes, int n_in,
                              void* d_out, int out_size) {
    // Resolve inputs by unique element counts; fall back to positional order.
    const float* coef = nullptr;
    const float* x    = nullptr;
    const float* W    = nullptr;
    const float* Bb   = nullptr;
    for (int i = 0; i < n_in; ++i) {
        long long sz = in_sizes[i];
        if      (sz == (long long)NEXP)       coef = (const float*)d_in[i];
        else if (sz == (long long)BATCH * DM) x    = (const float*)d_in[i];
        else if (sz == 3LL * NEXP * DM * DM)  W    = (const float*)d_in[i];
        else if (sz == 3LL * DM)              Bb   = (const float*)d_in[i];
    }
    if (!coef || !x || !W || !Bb) {   // positional fallback (metadata order)
        coef = (const float*)d_in[0];
        x    = (const float*)d_in[1];
        W    = (const float*)d_in[2];
        Bb   = (const float*)d_in[3];
    }

    cudaFuncSetAttribute(gemm_kernel, cudaFuncAttributeMaxDynamicSharedMemorySize, SMEM_REQ);

    blend_kernel<<<(3 * DM * (DM / 4) + 255) / 256, 256>>>(coef, W);
    splitx_kernel<<<(BATCH * (DM / 4) + 255) / 256, 256>>>(x);

    dim3 grid(DM / BN, BATCH / BM);  // (16, 16) = 256 CTAs
    gemm_kernel<<<grid, NTHR, SMEM_REQ>>>(0, 0, Bb, nullptr);
    gemm_kernel<<<grid, NTHR, SMEM_REQ>>>(1, 1, Bb, nullptr);
    gemm_kernel<<<grid, NTHR, SMEM_REQ>>>(0, 2, Bb, (float*)d_out);
}

// round 9
// speedup vs baseline: 1.0982x; 1.0982x over previous
#include <cuda_runtime.h>
#include <cuda_bf16.h>
#include <stdint.h>

#define DI __device__ __forceinline__

static constexpr int BATCH  = 4096;
static constexpr int DM     = 2048;
static constexpr int NEXP   = 8;
static constexpr int KS     = 3 * DM;       // 6144 logical split-K
static constexpr int WK     = 2 * DM;       // 4096 dedup'd storage [hi|lo]
static constexpr int BM     = 128;
static constexpr int BN     = 128;
static constexpr int BK     = 64;           // bf16 per k-tile (128B row)
static constexpr int KT     = KS / BK;      // 96
static constexpr int STAGES = 3;
static constexpr int NTHR   = 256;

static constexpr int A_BYTES     = BM * 128;              // 16384
static constexpr int B_BYTES     = BN * 128;              // 16384
static constexpr int STAGE_BYTES = A_BYTES + B_BYTES;     // 32768
static constexpr int SMEM_STAGES = STAGES * STAGE_BYTES;  // 98304
static constexpr int SMEM_REQ    = SMEM_STAGES + 1024;    // pad for 1KB align

// ---------------- device scratch (dedup: hi stored once) ----------------
__device__ __nv_bfloat16 g_W [(unsigned long long)3 * DM * WK];   // [wh|wl]
__device__ __nv_bfloat16 g_Xa[(unsigned long long)BATCH * WK];    // [xh|xl] ping
__device__ __nv_bfloat16 g_Xb[(unsigned long long)BATCH * WK];    // [xh|xl] pong

// ---------------- helpers ----------------
DI uint32_t smem_u32(const void* p) {
    uint32_t a;
    asm("{ .reg .u64 t; cvta.to.shared.u64 t, %1; cvt.u32.u64 %0, t; }" : "=r"(a) : "l"(p));
    return a;
}
DI uint32_t swz(uint32_t off) { return off ^ ((off >> 3) & 0x70); }  // SW128

DI void cp16(uint32_t s, const void* g) {
    asm volatile("cp.async.cg.shared.global [%0], [%1], 16;\n" :: "r"(s), "l"(g));
}
DI void cp_commit() { asm volatile("cp.async.commit_group;\n" ::); }
template <int N> DI void cp_wait() { asm volatile("cp.async.wait_group %0;\n" :: "n"(N)); }

DI void ldsm4(uint32_t& r0, uint32_t& r1, uint32_t& r2, uint32_t& r3, uint32_t addr) {
    asm volatile("ldmatrix.sync.aligned.m8n8.x4.shared.b16 {%0,%1,%2,%3}, [%4];"
                 : "=r"(r0), "=r"(r1), "=r"(r2), "=r"(r3) : "r"(addr));
}
DI void mma16816(float* d, uint32_t a0, uint32_t a1, uint32_t a2, uint32_t a3,
                 uint32_t b0, uint32_t b1) {
    asm volatile(
        "mma.sync.aligned.m16n8k16.row.col.f32.bf16.bf16.f32 "
        "{%0,%1,%2,%3}, {%4,%5,%6,%7}, {%8,%9}, {%0,%1,%2,%3};"
        : "+f"(d[0]), "+f"(d[1]), "+f"(d[2]), "+f"(d[3])
        : "r"(a0), "r"(a1), "r"(a2), "r"(a3), "r"(b0), "r"(b1));
}

DI uint32_t pack_bf2(__nv_bfloat16 a, __nv_bfloat16 b) {
    return (uint32_t)__bfloat16_as_ushort(a) | ((uint32_t)__bfloat16_as_ushort(b) << 16);
}
DI void split1(float v, __nv_bfloat16& h, __nv_bfloat16& l) {
    h = __float2bfloat16(v);
    l = __float2bfloat16(v - __bfloat162float(h));
}

// ---------------- blend: Wd[l] = [wh | wl] of sum_e c_e W[l,e] ----------------
__global__ void blend_kernel(const float* __restrict__ coef, const float* __restrict__ W) {
    long long idx = (long long)blockIdx.x * blockDim.x + threadIdx.x;
    const long long total = 3LL * DM * (DM / 4);
    if (idx >= total) return;
    int       i4 = (int)(idx % (DM / 4));
    long long t  = idx / (DM / 4);
    int       o  = (int)(t % DM);
    int       l  = (int)(t / DM);

    float c[NEXP];
#pragma unroll
    for (int e = 0; e < NEXP; ++e) c[e] = __ldg(coef + e);

    const float* base = W + ((size_t)l * NEXP) * DM * DM + (size_t)o * DM + (size_t)i4 * 4;
    float4 acc = make_float4(0.f, 0.f, 0.f, 0.f);
#pragma unroll
    for (int e = 0; e < NEXP; ++e) {
        float4 v = __ldg((const float4*)(base + (size_t)e * DM * DM));
        acc.x += c[e] * v.x; acc.y += c[e] * v.y;
        acc.z += c[e] * v.z; acc.w += c[e] * v.w;
    }
    __nv_bfloat16 h[4], lo[4];
    split1(acc.x, h[0], lo[0]); split1(acc.y, h[1], lo[1]);
    split1(acc.z, h[2], lo[2]); split1(acc.w, h[3], lo[3]);

    __nv_bfloat16* row = g_W + ((size_t)l * DM + o) * WK;
    int n = i4 * 4;
    *(uint2*)&row[n]      = make_uint2(pack_bf2(h[0], h[1]),  pack_bf2(h[2], h[3]));
    *(uint2*)&row[DM + n] = make_uint2(pack_bf2(lo[0], lo[1]), pack_bf2(lo[2], lo[3]));
}

// ---------------- split input x -> Xa = [xh | xl] ----------------
__global__ void splitx_kernel(const float* __restrict__ x) {
    long long idx = (long long)blockIdx.x * blockDim.x + threadIdx.x;
    const long long total = (long long)BATCH * (DM / 4);
    if (idx >= total) return;
    int i4 = (int)(idx % (DM / 4));
    int r  = (int)(idx / (DM / 4));
    float4 v = __ldg((const float4*)(x + (size_t)r * DM) + i4);
    __nv_bfloat16 h[4], lo[4];
    split1(v.x, h[0], lo[0]); split1(v.y, h[1], lo[1]);
    split1(v.z, h[2], lo[2]); split1(v.w, h[3], lo[3]);
    __nv_bfloat16* row = g_Xa + (size_t)r * WK;
    int n = i4 * 4;
    *(uint2*)&row[n]      = make_uint2(pack_bf2(h[0], h[1]),  pack_bf2(h[2], h[3]));
    *(uint2*)&row[DM + n] = make_uint2(pack_bf2(lo[0], lo[1]), pack_bf2(lo[2], lo[3]));
}

// ---------------- GEMM: 128x128 tile, logical K=6144 over dedup'd [hi|lo] ----------------
// Schedule: t in [0,32): xh*wh; [32,64): xh*wl; [64,96): xl*wh.
// Remap: tA = t<32 ? t : t-32 ; tB = t<64 ? t : t-64.
// 8 warps, warp grid 4(m)x2(n), warp tile 32x64. 2 CTAs/SM (regs<=128, 97KB smem).
__global__ void __launch_bounds__(NTHR, 2)
gemm_kernel(int src_sel, int layer, const float* __restrict__ bias_all,
            float* __restrict__ out_f) {
    const __nv_bfloat16* A  = src_sel ? g_Xb : g_Xa;
    __nv_bfloat16*       Xn = src_sel ? g_Xa : g_Xb;
    const __nv_bfloat16* Bw = g_W + (size_t)layer * DM * WK;
    const float*         bias = bias_all + layer * DM;
    const bool final_layer = (out_f != nullptr);

    extern __shared__ char smraw[];
    uint32_t sb = (smem_u32(smraw) + 1023u) & ~1023u;

    const int tid  = threadIdx.x;
    const int wid  = tid >> 5;
    const int lane = tid & 31;
    const int wm   = wid & 3;         // m warp (32 rows each)
    const int wn   = wid >> 2;        // n warp (64 cols each)
    const int m_base = blockIdx.y * BM;
    const int n_base = blockIdx.x * BN;

    // ---- cp.async geometry: A and B have identical 128x128B tiles ----
    const int r0 = tid >> 3;              // rows 0..31 (+32 per chunk)
    const int cbyte = (tid & 7) * 16;
    const char* gA = (const char*)(A  + (size_t)(m_base + r0) * WK) + cbyte;
    const char* gB = (const char*)(Bw + (size_t)(n_base + r0) * WK) + cbyte;
    uint32_t soff[4];
#pragma unroll
    for (int j = 0; j < 4; ++j) soff[j] = swz((uint32_t)(r0 + 32 * j) * 128 + cbyte);
    const size_t rowstep = (size_t)32 * WK * 2;   // 32 rows in bytes

#define LOAD_TILE(T)                                                              \
    do {                                                                          \
        int _t  = (T);                                                            \
        int _ta = (_t < 32) ? _t : _t - 32;   /* A: [xh|xl] remap */              \
        int _tb = (_t < 64) ? _t : _t - 64;   /* B: [wh|wl] remap */              \
        uint32_t _sa = sb + (_t % 3) * STAGE_BYTES;                               \
        uint32_t _sb = _sa + A_BYTES;                                             \
        const char* _ga = gA + (size_t)_ta * (BK * 2);                            \
        const char* _gb = gB + (size_t)_tb * (BK * 2);                            \
        _Pragma("unroll")                                                         \
        for (int _j = 0; _j < 4; ++_j) cp16(_sa + soff[_j], _ga + _j * rowstep);  \
        _Pragma("unroll")                                                         \
        for (int _j = 0; _j < 4; ++_j) cp16(_sb + soff[_j], _gb + _j * rowstep);  \
        cp_commit();                                                              \
    } while (0)

    // ---- ldmatrix geometry ----
    const int t4  = lane >> 3;
    const int r8  = lane & 7;
    const uint32_t xorw = (uint32_t)r8 << 4;   // swizzle XOR (row&7)<<4
    uint32_t aoff[2], boff[4];
#pragma unroll
    for (int mi = 0; mi < 2; ++mi) {
        int row = wm * 32 + mi * 16 + (t4 & 1) * 8 + r8;
        aoff[mi] = (uint32_t)row * 128 + (uint32_t)(t4 >> 1) * 16;
    }
#pragma unroll
    for (int np = 0; np < 4; ++np) {
        int row = wn * 64 + np * 16 + (t4 >> 1) * 8 + r8;
        boff[np] = (uint32_t)row * 128 + (uint32_t)(t4 & 1) * 16;
    }

    float acc[2][8][4];
#pragma unroll
    for (int i = 0; i < 2; ++i)
#pragma unroll
        for (int j = 0; j < 8; ++j)
#pragma unroll
            for (int q = 0; q < 4; ++q) acc[i][j][q] = 0.f;

    // ---- pipeline: 3 stages, 2 in flight ----
    LOAD_TILE(0); LOAD_TILE(1);

    for (int t = 0; t < KT; ++t) {
        if (t < KT - 1) cp_wait<1>();
        else            cp_wait<0>();
        __syncthreads();
        if (t + 2 < KT) LOAD_TILE(t + 2);

        uint32_t sa = sb + (t % 3) * STAGE_BYTES;
        uint32_t sB = sa + A_BYTES;
#pragma unroll
        for (int k16 = 0; k16 < 4; ++k16) {
            uint32_t a[2][4];
#pragma unroll
            for (int mi = 0; mi < 2; ++mi)
                ldsm4(a[mi][0], a[mi][1], a[mi][2], a[mi][3],
                      sa + ((aoff[mi] + k16 * 32) ^ xorw));
            uint32_t b[4][4];
#pragma unroll
            for (int np = 0; np < 4; ++np)
                ldsm4(b[np][0], b[np][1], b[np][2], b[np][3],
                      sB + ((boff[np] + k16 * 32) ^ xorw));
#pragma unroll
            for (int mi = 0; mi < 2; ++mi)
#pragma unroll
                for (int np = 0; np < 4; ++np) {
                    mma16816(acc[mi][2 * np],     a[mi][0], a[mi][1], a[mi][2], a[mi][3],
                             b[np][0], b[np][1]);
                    mma16816(acc[mi][2 * np + 1], a[mi][0], a[mi][1], a[mi][2], a[mi][3],
                             b[np][2], b[np][3]);
                }
        }
    }

    // ---- epilogue ----
    const int gid = lane >> 2;
    const int tig = lane & 3;

    float bw0[8], bw1[8];
#pragma unroll
    for (int nj = 0; nj < 8; ++nj) {
        int col = n_base + wn * 64 + nj * 8 + 2 * tig;
        bw0[nj] = __ldg(bias + col);
        bw1[nj] = __ldg(bias + col + 1);
    }

    if (!final_layer) {
#pragma unroll
        for (int mi = 0; mi < 2; ++mi) {
            int row0 = m_base + wm * 32 + mi * 16 + gid;
            __nv_bfloat16* xr0 = Xn + (size_t)row0 * WK;
            __nv_bfloat16* xr1 = Xn + (size_t)(row0 + 8) * WK;
#pragma unroll
            for (int nj = 0; nj < 8; ++nj) {
                int n = wn * 64 + nj * 8 + 2 * tig + n_base;
                float v0 = acc[mi][nj][0] + bw0[nj];
                float v1 = acc[mi][nj][1] + bw1[nj];
                float v2 = acc[mi][nj][2] + bw0[nj];
                float v3 = acc[mi][nj][3] + bw1[nj];
                v0 = (v0 > 0.f) ? v0 : expm1f(v0);
                v1 = (v1 > 0.f) ? v1 : expm1f(v1);
                v2 = (v2 > 0.f) ? v2 : expm1f(v2);
                v3 = (v3 > 0.f) ? v3 : expm1f(v3);
                __nv_bfloat16 h0, l0, h1, l1, h2, l2, h3, l3;
                split1(v0, h0, l0); split1(v1, h1, l1);
                split1(v2, h2, l2); split1(v3, h3, l3);
                *(uint32_t*)&xr0[n]      = pack_bf2(h0, h1);
                *(uint32_t*)&xr0[DM + n] = pack_bf2(l0, l1);
                *(uint32_t*)&xr1[n]      = pack_bf2(h2, h3);
                *(uint32_t*)&xr1[DM + n] = pack_bf2(l2, l3);
            }
        }
    } else {
#pragma unroll
        for (int mi = 0; mi < 2; ++mi) {
            int row0 = m_base + wm * 32 + mi * 16 + gid;
            float* o0 = out_f + (size_t)row0 * DM;
            float* o1 = out_f + (size_t)(row0 + 8) * DM;
#pragma unroll
            for (int nj = 0; nj < 8; ++nj) {
                int n = n_base + wn * 64 + nj * 8 + 2 * tig;
                float2 u0 = { acc[mi][nj][0] + bw0[nj], acc[mi][nj][1] + bw1[nj] };
                float2 u1 = { acc[mi][nj][2] + bw0[nj], acc[mi][nj][3] + bw1[nj] };
                *(float2*)&o0[n] = u0;
                *(float2*)&o1[n] = u1;
            }
        }
    }
#undef LOAD_TILE
}

// ---------------- host launch ----------------
extern "C" void kernel_launch(void* const* d_in, const int* in_sizes, int n_in,
                              void* d_out, int out_size) {
    const float* coef = nullptr;
    const float* x    = nullptr;
    const float* W    = nullptr;
    const float* Bb   = nullptr;
    for (int i = 0; i < n_in; ++i) {
        long long sz = in_sizes[i];
        if      (sz == (long long)NEXP)       coef = (const float*)d_in[i];
        else if (sz == (long long)BATCH * DM) x    = (const float*)d_in[i];
        else if (sz == 3LL * NEXP * DM * DM)  W    = (const float*)d_in[i];
        else if (sz == 3LL * DM)              Bb   = (const float*)d_in[i];
    }
    if (!coef || !x || !W || !Bb) {
        coef = (const float*)d_in[0];
        x    = (const float*)d_in[1];
        W    = (const float*)d_in[2];
        Bb   = (const float*)d_in[3];
    }

    cudaFuncSetAttribute(gemm_kernel, cudaFuncAttributeMaxDynamicSharedMemorySize, SMEM_REQ);

    blend_kernel<<<(3 * DM * (DM / 4) + 255) / 256, 256>>>(coef, W);
    splitx_kernel<<<(BATCH * (DM / 4) + 255) / 256, 256>>>(x);

    dim3 grid(DM / BN, BATCH / BM);  // (16, 32) = 512 CTAs
    gemm_kernel<<<grid, NTHR, SMEM_REQ>>>(0, 0, Bb, nullptr);
    gemm_kernel<<<grid, NTHR, SMEM_REQ>>>(1, 1, Bb, nullptr);
    gemm_kernel<<<grid, NTHR, SMEM_REQ>>>(0, 2, Bb, (float*)d_out);
}